// round 17
// baseline (speedup 1.0000x reference)
#include <cuda_runtime.h>
#include <cuda_bf16.h>
#include <math.h>
#include <stdint.h>

#define B 64
#define TT 512
#define E 128
#define H 256

typedef unsigned long long u64;

// ---------------- packed f32x2 helpers ----------------------------------------
__device__ __forceinline__ u64 ffma2(u64 a, u64 b, u64 c) {
    u64 d;
    asm("fma.rn.f32x2 %0, %1, %2, %3;" : "=l"(d) : "l"(a), "l"(b), "l"(c));
    return d;
}
__device__ __forceinline__ u64 fadd2(u64 a, u64 b) {
    u64 d;
    asm("add.rn.f32x2 %0, %1, %2;" : "=l"(d) : "l"(a), "l"(b));
    return d;
}
__device__ __forceinline__ float2 unpk(u64 v) {
    float2 r;
    asm("mov.b64 {%0, %1}, %2;" : "=f"(r.x), "=f"(r.y) : "l"(v));
    return r;
}
__device__ __forceinline__ float fast_tanh(float x) {
    float e, r;
    asm("ex2.approx.f32 %0, %1;" : "=f"(e) : "f"(x * 2.885390081777927f));
    asm("rcp.approx.f32 %0, %1;" : "=f"(r) : "f"(e + 1.0f));
    return fmaf(-2.0f, r, 1.0f);
}

// bf16 hi/lo packing (4 values per u64)
__device__ __forceinline__ u64 pack4bf_hi(float4 v) {
    unsigned short s0 = __bfloat16_as_ushort(__float2bfloat16(v.x));
    unsigned short s1 = __bfloat16_as_ushort(__float2bfloat16(v.y));
    unsigned short s2 = __bfloat16_as_ushort(__float2bfloat16(v.z));
    unsigned short s3 = __bfloat16_as_ushort(__float2bfloat16(v.w));
    return (u64)s0 | ((u64)s1 << 16) | ((u64)s2 << 32) | ((u64)s3 << 48);
}
__device__ __forceinline__ u64 pack4bf_lo(float4 v) {
    float r0 = v.x - __bfloat162float(__float2bfloat16(v.x));
    float r1 = v.y - __bfloat162float(__float2bfloat16(v.y));
    float r2 = v.z - __bfloat162float(__float2bfloat16(v.z));
    float r3 = v.w - __bfloat162float(__float2bfloat16(v.w));
    unsigned short s0 = __bfloat16_as_ushort(__float2bfloat16(r0));
    unsigned short s1 = __bfloat16_as_ushort(__float2bfloat16(r1));
    unsigned short s2 = __bfloat16_as_ushort(__float2bfloat16(r2));
    unsigned short s3 = __bfloat16_as_ushort(__float2bfloat16(r3));
    return (u64)s0 | ((u64)s1 << 16) | ((u64)s2 << 32) | ((u64)s3 << 48);
}

// warp-level bf16 MMA (sm_80+ path, valid on plain sm_103) — layout proven R14
#define MMA_BF16(c, a0, a1, a2, a3, b0, b1)                                    \
    asm volatile(                                                              \
        "mma.sync.aligned.m16n8k16.row.col.f32.bf16.bf16.f32 "                 \
        "{%0,%1,%2,%3}, {%4,%5,%6,%7}, {%8,%9}, {%0,%1,%2,%3};\n"              \
        : "+f"((c)[0]), "+f"((c)[1]), "+f"((c)[2]), "+f"((c)[3])               \
        : "r"(a0), "r"(a1), "r"(a2), "r"(a3), "r"(b0), "r"(b1))

// ---------------- scratch (device globals) ------------------------------------
__device__ float g_xp1f[(size_t)B * TT * H];
__device__ float g_xp1b[(size_t)B * TT * H];
__device__ float g_o1[(size_t)B * TT * 2 * H];
__device__ float g_xp2f[(size_t)B * TT * H];
__device__ float g_xp2b[(size_t)B * TT * H];

__device__ float g_msum[2 * B * H];              // per (b,dir): sum_t h
__device__ float g_last[2 * B * H];              // per (b,dir): h at t=TT-1

__device__ float2 g_w1p[512 * 512];
__device__ float2 g_w2p[256 * 256];
__device__ float g_b1f[H], g_b1b[H], g_b2f[H], g_b2b[H];

// bf16 hi/lo split weights. layer2 in-proj: [n=256][k512/4=128] u64
__device__ u64 g_w2fh[256 * 128];
__device__ u64 g_w2fl[256 * 128];
__device__ u64 g_w2bh[256 * 128];
__device__ u64 g_w2bl[256 * 128];
// layer1 in-proj: [n=256][k128/4=32] u64
__device__ u64 g_r1fh[256 * 32];
__device__ u64 g_r1fl[256 * 32];
__device__ u64 g_r1bh[256 * 32];
__device__ u64 g_r1bl[256 * 32];

// ---------------- prep --------------------------------------------------------
__global__ void prep_kernel(
    const float* __restrict__ r1_wif, const float* __restrict__ r1_wib,
    const float* __restrict__ r1_bif, const float* __restrict__ r1_bhf,
    const float* __restrict__ r1_bib, const float* __restrict__ r1_bhb,
    const float* __restrict__ r2_wif, const float* __restrict__ r2_wib,
    const float* __restrict__ r2_bif, const float* __restrict__ r2_bhf,
    const float* __restrict__ r2_bib, const float* __restrict__ r2_bhb,
    const float* __restrict__ w1, const float* __restrict__ w2)
{
    int i = blockIdx.x * 256 + threadIdx.x;
    if (i < 256 * 32) {
        float4 vf = *(const float4*)(r1_wif + (size_t)i * 4);
        float4 vb = *(const float4*)(r1_wib + (size_t)i * 4);
        g_r1fh[i] = pack4bf_hi(vf);
        g_r1fl[i] = pack4bf_lo(vf);
        g_r1bh[i] = pack4bf_hi(vb);
        g_r1bl[i] = pack4bf_lo(vb);
    }
    if (i < 256 * H) {
        int kp = i >> 8, j = i & 255;
        g_w2p[i] = make_float2(w2[j * 512 + 2 * kp], w2[j * 512 + 2 * kp + 1]);
    }
    if (i < 256 * 128) {
        float4 vf = *(const float4*)(r2_wif + (size_t)i * 4);
        float4 vb = *(const float4*)(r2_wib + (size_t)i * 4);
        g_w2fh[i] = pack4bf_hi(vf);
        g_w2fl[i] = pack4bf_lo(vf);
        g_w2bh[i] = pack4bf_hi(vb);
        g_w2bl[i] = pack4bf_lo(vb);
    }
    if (i < 512 * 512) {
        int kp = i >> 9, o = i & 511;
        g_w1p[i] = make_float2(w1[o * 1024 + 2 * kp], w1[o * 1024 + 2 * kp + 1]);
    }
    if (i < H) {
        g_b1f[i] = r1_bif[i] + r1_bhf[i];
        g_b1b[i] = r1_bib[i] + r1_bhb[i];
        g_b2f[i] = r2_bif[i] + r2_bhf[i];
        g_b2b[i] = r2_bib[i] + r2_bhb[i];
    }
}

// ---------------- shared MMA-projection geometry -------------------------------
// A chunk: 64 rows x 64 k bf16, row stride 72 elems (bank-conflict-free).
// B chunk: 128 rows x 64 k bf16, stride 72.
static constexpr int SA_SZ = 64 * 72 * 2;            // 9216
static constexpr int SB_SZ = 128 * 72 * 2;           // 18432
static constexpr int SB_BASE = 4 * SA_SZ;            // 36864
static constexpr int PJ_SMEM = SB_BASE + 4 * SB_SZ;  // 110592
#define SA_H(buf) ((buf) * 2 * SA_SZ)
#define SA_L(buf) ((buf) * 2 * SA_SZ + SA_SZ)
#define SB_H(buf) (SB_BASE + (buf) * 2 * SB_SZ)
#define SB_L(buf) (SB_BASE + (buf) * 2 * SB_SZ + SB_SZ)

// compute one (m64 x n128 x k64) stage into acc[2][2][4]
#define PJ_COMPUTE(accn, sah, sal, sbh, sbl)                                   \
    do {                                                                       \
        _Pragma("unroll")                                                      \
        for (int ks = 0; ks < 4; ks++) {                                       \
            uint32_t ah[2][4], al[2][4];                                       \
            _Pragma("unroll")                                                  \
            for (int mt = 0; mt < 2; mt++) {                                   \
                uint32_t ba = (uint32_t)(((M0 + mt * 16 + r4) * 72 + ks * 16 + kp2) * 2); \
                ah[mt][0] = *(const uint32_t*)(smem + (sah) + ba);             \
                ah[mt][1] = *(const uint32_t*)(smem + (sah) + ba + 1152);      \
                ah[mt][2] = *(const uint32_t*)(smem + (sah) + ba + 16);        \
                ah[mt][3] = *(const uint32_t*)(smem + (sah) + ba + 1168);      \
                al[mt][0] = *(const uint32_t*)(smem + (sal) + ba);             \
                al[mt][1] = *(const uint32_t*)(smem + (sal) + ba + 1152);      \
                al[mt][2] = *(const uint32_t*)(smem + (sal) + ba + 16);        \
                al[mt][3] = *(const uint32_t*)(smem + (sal) + ba + 1168);      \
            }                                                                  \
            _Pragma("unroll")                                                  \
            for (int nt = 0; nt < 2; nt++) {                                   \
                uint32_t bb = (uint32_t)(((N0 + nt * 8 + r4) * 72 + ks * 16 + kp2) * 2); \
                uint32_t bh0 = *(const uint32_t*)(smem + (sbh) + bb);          \
                uint32_t bh1 = *(const uint32_t*)(smem + (sbh) + bb + 16);     \
                uint32_t bl0 = *(const uint32_t*)(smem + (sbl) + bb);          \
                uint32_t bl1 = *(const uint32_t*)(smem + (sbl) + bb + 16);     \
                _Pragma("unroll")                                              \
                for (int mt = 0; mt < 2; mt++) {                               \
                    MMA_BF16((accn)[mt][nt], ah[mt][0], ah[mt][1], ah[mt][2], ah[mt][3], bh0, bh1); \
                    MMA_BF16((accn)[mt][nt], ah[mt][0], ah[mt][1], ah[mt][2], ah[mt][3], bl0, bl1); \
                    MMA_BF16((accn)[mt][nt], al[mt][0], al[mt][1], al[mt][2], al[mt][3], bh0, bh1); \
                }                                                              \
            }                                                                  \
        }                                                                      \
    } while (0)

// ---------------- layer-2 input projection: HMMA (R15-proven version) ---------
__global__ __launch_bounds__(512, 1) void proj2_mma_kernel()
{
    extern __shared__ char smem[];
    int tid = threadIdx.x;
    int wid = tid >> 5, lane = tid & 31;
    int r4 = lane >> 2;
    int kp2 = (lane & 3) * 2;
    int tok0 = blockIdx.x * 64;
    int M0 = (wid & 1) * 32;
    int N0 = (wid >> 1) * 16;

    float acc[4][2][2][4];
#pragma unroll
    for (int nc = 0; nc < 4; nc++)
#pragma unroll
        for (int mt = 0; mt < 2; mt++)
#pragma unroll
            for (int nt = 0; nt < 2; nt++)
#pragma unroll
                for (int q = 0; q < 4; q++) acc[nc][mt][nt][q] = 0.f;

    auto stageA = [&](int kc, int buf) {
#pragma unroll
        for (int idx = tid; idx < 64 * 16; idx += 512) {
            int m = idx >> 4, q = idx & 15;
            float4 v = *(const float4*)(g_o1 + (size_t)(tok0 + m) * 512 + kc * 64 + q * 4);
            uint32_t off = (uint32_t)(m * 144 + q * 8);
            *(u64*)(smem + SA_H(buf) + off) = pack4bf_hi(v);
            *(u64*)(smem + SA_L(buf) + off) = pack4bf_lo(v);
        }
    };
    auto stageB = [&](int kc, int nc, int buf) {
        const u64* gh = (nc < 2) ? g_w2fh : g_w2bh;
        const u64* gl = (nc < 2) ? g_w2fl : g_w2bl;
        int nb = (nc & 1) * 128;
#pragma unroll
        for (int idx = tid; idx < 128 * 16; idx += 512) {
            int n = idx >> 4, kq = idx & 15;
            size_t gi = (size_t)(nb + n) * 128 + kc * 16 + kq;
            uint32_t off = (uint32_t)(n * 144 + kq * 8);
            *(u64*)(smem + SB_H(buf) + off) = gh[gi];
            *(u64*)(smem + SB_L(buf) + off) = gl[gi];
        }
    };

    stageA(0, 0);
    stageB(0, 0, 0);
    __syncthreads();

    for (int kc = 0; kc < 8; kc++) {
        int ab = kc & 1;
#pragma unroll
        for (int nc = 0; nc < 4; nc++) {
            int it = kc * 4 + nc;
            int bbuf = it & 1;
            if (it < 31) {
                int nkc = (nc == 3) ? kc + 1 : kc;
                int nnc = (nc == 3) ? 0 : nc + 1;
                stageB(nkc, nnc, bbuf ^ 1);
            }
            if (nc == 0 && kc < 7) stageA(kc + 1, ab ^ 1);
            PJ_COMPUTE(acc[nc], SA_H(ab), SA_L(ab), SB_H(bbuf), SB_L(bbuf));
            __syncthreads();
        }
    }

#pragma unroll
    for (int nc = 0; nc < 4; nc++) {
        float* outp = (nc < 2) ? g_xp2f : g_xp2b;
        const float* bias = (nc < 2) ? g_b2f : g_b2b;
        int nb = (nc & 1) * 128;
#pragma unroll
        for (int mt = 0; mt < 2; mt++)
#pragma unroll
            for (int nt = 0; nt < 2; nt++) {
                int gcol = nb + N0 + nt * 8 + kp2;
                int row0 = tok0 + M0 + mt * 16 + r4;
                float b0 = bias[gcol], b1v = bias[gcol + 1];
                *(float2*)(outp + (size_t)row0 * H + gcol) =
                    make_float2(acc[nc][mt][nt][0] + b0, acc[nc][mt][nt][1] + b1v);
                *(float2*)(outp + (size_t)(row0 + 8) * H + gcol) =
                    make_float2(acc[nc][mt][nt][2] + b0, acc[nc][mt][nt][3] + b1v);
            }
    }
}

// ---------------- layer-1 input projection: HMMA (R15-proven) -----------------
__global__ __launch_bounds__(512, 1) void proj1_mma_kernel(
    const int* __restrict__ x, const float* __restrict__ emb)
{
    extern __shared__ char smem[];
    int tid = threadIdx.x;
    int wid = tid >> 5, lane = tid & 31;
    int r4 = lane >> 2;
    int kp2 = (lane & 3) * 2;
    int tok0 = blockIdx.x * 64;
    int M0 = (wid & 1) * 32;
    int N0 = (wid >> 1) * 16;

    float acc[4][2][2][4];
#pragma unroll
    for (int nc = 0; nc < 4; nc++)
#pragma unroll
        for (int mt = 0; mt < 2; mt++)
#pragma unroll
            for (int nt = 0; nt < 2; nt++)
#pragma unroll
                for (int q = 0; q < 4; q++) acc[nc][mt][nt][q] = 0.f;

    auto stageA = [&](int kc, int buf) {
#pragma unroll
        for (int idx = tid; idx < 64 * 16; idx += 512) {
            int m = idx >> 4, q = idx & 15;
            int token = x[tok0 + m];
            float4 v = *(const float4*)(emb + (size_t)token * 128 + kc * 64 + q * 4);
            uint32_t off = (uint32_t)(m * 144 + q * 8);
            *(u64*)(smem + SA_H(buf) + off) = pack4bf_hi(v);
            *(u64*)(smem + SA_L(buf) + off) = pack4bf_lo(v);
        }
    };
    auto stageB = [&](int kc, int nc, int buf) {
        const u64* gh = (nc < 2) ? g_r1fh : g_r1bh;
        const u64* gl = (nc < 2) ? g_r1fl : g_r1bl;
        int nb = (nc & 1) * 128;
#pragma unroll
        for (int idx = tid; idx < 128 * 16; idx += 512) {
            int n = idx >> 4, kq = idx & 15;
            size_t gi = (size_t)(nb + n) * 32 + kc * 16 + kq;
            uint32_t off = (uint32_t)(n * 144 + kq * 8);
            *(u64*)(smem + SB_H(buf) + off) = gh[gi];
            *(u64*)(smem + SB_L(buf) + off) = gl[gi];
        }
    };

    stageA(0, 0);
    stageB(0, 0, 0);
    __syncthreads();

    for (int kc = 0; kc < 2; kc++) {
        int ab = kc & 1;
#pragma unroll
        for (int nc = 0; nc < 4; nc++) {
            int it = kc * 4 + nc;
            int bbuf = it & 1;
            if (it < 7) {
                int nkc = (nc == 3) ? kc + 1 : kc;
                int nnc = (nc == 3) ? 0 : nc + 1;
                stageB(nkc, nnc, bbuf ^ 1);
            }
            if (nc == 0 && kc < 1) stageA(kc + 1, ab ^ 1);
            PJ_COMPUTE(acc[nc], SA_H(ab), SA_L(ab), SB_H(bbuf), SB_L(bbuf));
            __syncthreads();
        }
    }

#pragma unroll
    for (int nc = 0; nc < 4; nc++) {
        float* outp = (nc < 2) ? g_xp1f : g_xp1b;
        const float* bias = (nc < 2) ? g_b1f : g_b1b;
        int nb = (nc & 1) * 128;
#pragma unroll
        for (int mt = 0; mt < 2; mt++)
#pragma unroll
            for (int nt = 0; nt < 2; nt++) {
                int gcol = nb + N0 + nt * 8 + kp2;
                int row0 = tok0 + M0 + mt * 16 + r4;
                float b0 = bias[gcol], b1v = bias[gcol + 1];
                *(float2*)(outp + (size_t)row0 * H + gcol) =
                    make_float2(acc[nc][mt][nt][0] + b0, acc[nc][mt][nt][1] + b1v);
                *(float2*)(outp + (size_t)(row0 + 8) * H + gcol) =
                    make_float2(acc[nc][mt][nt][2] + b0, acc[nc][mt][nt][3] + b1v);
            }
    }
}

// ---------------- recurrence: lane-interleaved split-K, 1 barrier/step --------
// Thread (j = tid>>1, half = tid&1): halves are ADJACENT LANES, so the partial
// exchange is a single shfl.bfly(1) instead of STS+BAR+LDS. Both threads of a
// pair compute hn; half0 writes hb, half1 writes out / accumulates mean+last.
// Weight allocation per thread identical to proven R7: PREG=40 reg pairs +
// PSM=24 smem pairs (12 ulonglong2 slots).
constexpr int PREG = 40;
constexpr int PSM = 24;
constexpr int WSLOT = PSM / 2;
constexpr int RNN_SMEM_BYTES = 2 * WSLOT * H * 16 + 2 * H * 4;

__global__ __launch_bounds__(512, 1) void rnn_kernel(
    const float* __restrict__ whh_f, const float* __restrict__ whh_b, int layer)
{
    extern __shared__ char smraw[];
    ulonglong2* wsq = (ulonglong2*)smraw;                 // [24][256]
    float* hb = (float*)(smraw + 2 * WSLOT * H * 16);     // [2][256]

    int b = blockIdx.x >> 1;
    int dir = blockIdx.x & 1;
    const float* whh = dir ? whh_b : whh_f;
    const float* xp = layer ? (dir ? g_xp2b : g_xp2f) : (dir ? g_xp1b : g_xp1f);
    float* out = g_o1;                                    // layer-0 only

    int j = threadIdx.x >> 1;
    int half = threadIdx.x & 1;

    const u64* wrow = (const u64*)(whh + (size_t)j * H) + half * 64;
    u64 wr[PREG];
#pragma unroll
    for (int r = 0; r < PREG; r++) wr[r] = wrow[r];
#pragma unroll
    for (int i = 0; i < WSLOT; i++) {
        ulonglong2 v;
        v.x = wrow[PREG + 2 * i];
        v.y = wrow[PREG + 2 * i + 1];
        wsq[(half * WSLOT + i) * H + j] = v;
    }
    if (half == 0) { hb[j] = 0.f; hb[H + j] = 0.f; }
    __syncthreads();

    const float* xpBase = xp + (size_t)b * TT * H + j;
    float* outBase = out + (size_t)b * TT * (2 * H) + dir * H + j;
    const ulonglong2* wsBase = wsq + (half * WSLOT) * H + j;

    float xpv = (half == 0) ? xpBase[(size_t)(dir ? (TT - 1) : 0) * H] : 0.f;
    int lastS = dir ? 0 : (TT - 1);
    float hsum = 0.f, hlast = 0.f;

    int p = 0;
    for (int s = 0; s < TT; s++) {
        int t = dir ? (TT - 1 - s) : s;
        int sn = (s < TT - 1) ? (s + 1) : s;
        int tn = dir ? (TT - 1 - sn) : sn;
        float xpv_next = (half == 0) ? xpBase[(size_t)tn * H] : 0.f;

        const ulonglong2* h2 = (const ulonglong2*)(hb + p * H) + half * 32;
        u64 a0 = 0ull, a1 = 0ull, a2 = 0ull, a3 = 0ull;
#pragma unroll
        for (int q = 0; q < PREG / 2; q++) {
            ulonglong2 hq = h2[q];
            if (q & 1) {
                a2 = ffma2(hq.x, wr[2 * q], a2);
                a3 = ffma2(hq.y, wr[2 * q + 1], a3);
            } else {
                a0 = ffma2(hq.x, wr[2 * q], a0);
                a1 = ffma2(hq.y, wr[2 * q + 1], a1);
            }
        }
#pragma unroll
        for (int i = 0; i < WSLOT; i++) {
            ulonglong2 hq = h2[PREG / 2 + i];
            ulonglong2 wq = wsBase[i * H];
            if (i & 1) {
                a2 = ffma2(hq.x, wq.x, a2);
                a3 = ffma2(hq.y, wq.y, a3);
            } else {
                a0 = ffma2(hq.x, wq.x, a0);
                a1 = ffma2(hq.y, wq.y, a1);
            }
        }
        float2 f = unpk(fadd2(fadd2(a0, a1), fadd2(a2, a3)));
        float part = f.x + f.y + xpv;                      // xpv==0 for half 1
        float other = __shfl_xor_sync(0xffffffffu, part, 1);
        float hn = fast_tanh(part + other);
        if (half == 0) {
            hb[(p ^ 1) * H + j] = hn;
        } else if (layer == 0) {
            outBase[(size_t)t * (2 * H)] = hn;
        } else {
            hsum += hn;
            hlast = (s == lastS) ? hn : hlast;
        }
        __syncthreads();                                   // single barrier
        xpv = xpv_next;
        p ^= 1;
    }

    if (layer != 0 && half == 1) {
        g_msum[(b * 2 + dir) * H + j] = hsum;
        g_last[(b * 2 + dir) * H + j] = hlast;
    }
}

// ---------------- tail: small-array read + LN + FC1(relu) + FC2 ---------------
__global__ __launch_bounds__(256) void tail_kernel(
    const float* __restrict__ ln_g, const float* __restrict__ ln_b,
    const float* __restrict__ b1, const float* __restrict__ b2,
    float* __restrict__ outp)
{
    __shared__ __align__(16) float h_s[1024];
    __shared__ __align__(16) float hn_s[1024];
    __shared__ float red[256];
    __shared__ __align__(16) float r_s[512];
    int b = blockIdx.x, j = threadIdx.x;

    h_s[j]       = g_last[(b * 2 + 0) * H + j];
    h_s[H + j]   = g_last[(b * 2 + 1) * H + j];
    h_s[512 + j] = g_msum[(b * 2 + 0) * H + j] * (1.f / 512.f);
    h_s[768 + j] = g_msum[(b * 2 + 1) * H + j] * (1.f / 512.f);
    __syncthreads();

    red[j] = h_s[j] + h_s[j + 256] + h_s[j + 512] + h_s[j + 768];
    __syncthreads();
    for (int off = 128; off > 0; off >>= 1) {
        if (j < off) red[j] += red[j + off];
        __syncthreads();
    }
    float mu = red[0] * (1.f / 1024.f);
    __syncthreads();
    float d0 = h_s[j] - mu, d1 = h_s[j + 256] - mu,
          d2 = h_s[j + 512] - mu, d3 = h_s[j + 768] - mu;
    red[j] = d0 * d0 + d1 * d1 + d2 * d2 + d3 * d3;
    __syncthreads();
    for (int off = 128; off > 0; off >>= 1) {
        if (j < off) red[j] += red[j + off];
        __syncthreads();
    }
    float var = red[0] * (1.f / 1024.f);
    float sc = rsqrtf(var + 1e-5f);
    hn_s[j]       = d0 * sc * ln_g[j]       + ln_b[j];
    hn_s[j + 256] = d1 * sc * ln_g[j + 256] + ln_b[j + 256];
    hn_s[j + 512] = d2 * sc * ln_g[j + 512] + ln_b[j + 512];
    hn_s[j + 768] = d3 * sc * ln_g[j + 768] + ln_b[j + 768];
    __syncthreads();

    {
        const u64* hnu = (const u64*)hn_s;
        const u64* w1u = (const u64*)g_w1p;
        u64 acc0 = 0ull, acc1 = 0ull;
#pragma unroll 4
        for (int kp = 0; kp < 512; kp++) {
            u64 hv = hnu[kp];
            acc0 = ffma2(hv, w1u[kp * 512 + j], acc0);
            acc1 = ffma2(hv, w1u[kp * 512 + j + 256], acc1);
        }
        float2 f0 = unpk(acc0), f1 = unpk(acc1);
        r_s[j]       = fmaxf(f0.x + f0.y + b1[j], 0.f);
        r_s[j + 256] = fmaxf(f1.x + f1.y + b1[j + 256], 0.f);
    }
    __syncthreads();

    {
        const u64* rsu = (const u64*)r_s;
        const u64* w2u = (const u64*)g_w2p;
        u64 acc = 0ull;
#pragma unroll 4
        for (int kp = 0; kp < 256; kp++)
            acc = ffma2(rsu[kp], w2u[kp * 256 + j], acc);
        float2 f = unpk(acc);
        outp[b * 256 + j] = f.x + f.y + b2[j];
    }
}

// ---------------- launch ------------------------------------------------------
extern "C" void kernel_launch(void* const* d_in, const int* in_sizes, int n_in,
                              void* d_out, int out_size)
{
    const int*   x      = (const int*)  d_in[0];
    const float* emb    = (const float*)d_in[1];
    const float* r1_wif = (const float*)d_in[2];
    const float* r1_whf = (const float*)d_in[3];
    const float* r1_bif = (const float*)d_in[4];
    const float* r1_bhf = (const float*)d_in[5];
    const float* r1_wib = (const float*)d_in[6];
    const float* r1_whb = (const float*)d_in[7];
    const float* r1_bib = (const float*)d_in[8];
    const float* r1_bhb = (const float*)d_in[9];
    const float* r2_wif = (const float*)d_in[10];
    const float* r2_whf = (const float*)d_in[11];
    const float* r2_bif = (const float*)d_in[12];
    const float* r2_bhf = (const float*)d_in[13];
    const float* r2_wib = (const float*)d_in[14];
    const float* r2_whb = (const float*)d_in[15];
    const float* r2_bib = (const float*)d_in[16];
    const float* r2_bhb = (const float*)d_in[17];
    const float* ln_g   = (const float*)d_in[18];
    const float* ln_b   = (const float*)d_in[19];
    const float* w1     = (const float*)d_in[20];
    const float* b1     = (const float*)d_in[21];
    const float* w2     = (const float*)d_in[22];
    const float* b2     = (const float*)d_in[23];
    float* outp = (float*)d_out;

    cudaFuncSetAttribute(rnn_kernel,
                         cudaFuncAttributeMaxDynamicSharedMemorySize,
                         RNN_SMEM_BYTES);
    cudaFuncSetAttribute(proj2_mma_kernel,
                         cudaFuncAttributeMaxDynamicSharedMemorySize,
                         PJ_SMEM);
    cudaFuncSetAttribute(proj1_mma_kernel,
                         cudaFuncAttributeMaxDynamicSharedMemorySize,
                         PJ_SMEM);

    prep_kernel<<<1024, 256>>>(r1_wif, r1_wib, r1_bif, r1_bhf, r1_bib, r1_bhb,
                               r2_wif, r2_wib, r2_bif, r2_bhf, r2_bib, r2_bhb,
                               w1, w2);

    proj1_mma_kernel<<<(B * TT) / 64, 512, PJ_SMEM>>>(x, emb);
    rnn_kernel<<<2 * B, 512, RNN_SMEM_BYTES>>>(r1_whf, r1_whb, 0);
    proj2_mma_kernel<<<(B * TT) / 64, 512, PJ_SMEM>>>();
    rnn_kernel<<<2 * B, 512, RNN_SMEM_BYTES>>>(r2_whf, r2_whb, 1);
    tail_kernel<<<B, 256>>>(ln_g, ln_b, b1, b2, outp);
}